// round 9
// baseline (speedup 1.0000x reference)
#include <cuda_runtime.h>

#define BB 1024
#define DD 256
#define HH 32

// Column tables: exp(+W)/exp(-W) interleaved by j-pair, [16][DD] float2 — coalesced
// across k in the per-dim passes.  Row tables: [DD][HH] — coalesced across j for the
// rank-1 kstar-row gather.
__device__ float  g_ewp[HH * DD];
__device__ float  g_ewm[HH * DD];
__device__ float  g_ewpR[DD * HH];
__device__ float  g_ewmR[DD * HH];
__device__ float2 g_eb[DD];          // (exp(+b/2), exp(-b/2))
__device__ float  g_E[BB * HH];      // E_j(row) = exp((x@W)_j + c_j)

// Prep: blocks 0..7 build tables; blocks 8..8+BB/8-1 compute E, 8 rows per block.
__global__ __launch_bounds__(256) void prep_kernel(
    const float* __restrict__ x,
    const float* __restrict__ W,
    const float* __restrict__ b,
    const float* __restrict__ c)
{
    const int bid = blockIdx.x;
    const int tid = threadIdx.x;
    if (bid < 8) {
        for (int t = bid * 256 + tid; t < DD * HH; t += 8 * 256) {
            int d = t >> 5;
            int j = t & 31;
            float w  = W[t];
            float ep = expf(w);
            float em = expf(-w);
            int idx = (j >> 1) * (DD * 2) + d * 2 + (j & 1);
            g_ewp[idx] = ep;
            g_ewm[idx] = em;
            g_ewpR[t] = ep;          // t = d*HH + j: row-major copy
            g_ewmR[t] = em;
        }
        int t = bid * 256 + tid;
        if (t < DD) {
            float bv = b[t];
            g_eb[t] = make_float2(expf(0.5f * bv), expf(-0.5f * bv));
        }
        return;
    }

    // ---- E for 8 rows: warp w covers d in [32w,32w+32), lane = j.
    //      Each W value is loaded once and reused across 8 rows (8 masks). ----
    __shared__ float ap[8][8][32];           // [warp][row][j]
    const int row0 = (bid - 8) * 8;
    const int w    = tid >> 5;
    const int lane = tid & 31;

    unsigned m[8];
    #pragma unroll
    for (int r = 0; r < 8; ++r)
        m[r] = __ballot_sync(0xffffffffu, x[(row0 + r) * DD + w * 32 + lane] != 0.0f);

    const float* Wb = W + (w * 32) * HH + lane;
    float acc[8] = {0.f, 0.f, 0.f, 0.f, 0.f, 0.f, 0.f, 0.f};
    #pragma unroll
    for (int i = 0; i < 32; ++i) {
        float wv = Wb[i * HH];
        #pragma unroll
        for (int r = 0; r < 8; ++r)
            if (m[r] & (1u << i)) acc[r] += wv;
    }
    #pragma unroll
    for (int r = 0; r < 8; ++r) ap[w][r][lane] = acc[r];
    __syncthreads();

    // warp w finishes row (row0 + w)
    float a = c[lane];
    #pragma unroll
    for (int ww = 0; ww < 8; ++ww) a += ap[ww][w][lane];
    g_E[(row0 + w) * HH + lane] = expf(a);
}

__device__ __forceinline__ unsigned fmono(float f) {
    unsigned u = __float_as_uint(f);
    return (u & 0x80000000u) ? ~u : (u | 0x80000000u);
}

__global__ __launch_bounds__(128, 8) void gwg_kernel(
    const float* __restrict__ x,
    const float* __restrict__ gum,
    const float* __restrict__ acc,
    float* __restrict__ out)
{
    __shared__ float xs[DD];
    __shared__ __align__(16) float sEf[4][HH];   // per-warp copy of E_j
    __shared__ __align__(16) float sE2[4][HH];   // per-warp copy of E'_j
    __shared__ float sredf[4];
    __shared__ uint2 sredk[4];                   // (fmono(key), idx) per warp

    const int row  = blockIdx.x;
    const int tid  = threadIdx.x;
    const int w    = tid >> 5;
    const int lane = tid & 31;
    const int k0   = tid;          // dims tid and tid+128
    const int k1   = tid + 128;

    float  xk0 = x[row * DD + k0];
    float  xk1 = x[row * DD + k1];
    float2 eb0 = g_eb[k0];
    float2 eb1 = g_eb[k1];
    float  u0  = gum[row * DD + k0];
    float  u1  = gum[row * DD + k1];
    float  au  = acc[row];
    xs[k0] = xk0;
    xs[k1] = xk1;

    // each warp keeps its own E_lane and its own smem copy -> no cross-warp wait
    float E = g_E[row * HH + lane];
    sEf[w][lane] = E;
    __syncwarp();

    // ---- forward: p~_k = prod_j (1 + E_j e^{delta_k w_kj});  ek = eb * sqrt ----
    const float2* t0 = (const float2*)((xk0 == 0.0f) ? g_ewp : g_ewm);
    const float2* t1 = (const float2*)((xk1 == 0.0f) ? g_ewp : g_ewm);
    const float ebf0 = (xk0 == 0.0f) ? eb0.x : eb0.y;
    const float ebf1 = (xk1 == 0.0f) ? eb1.x : eb1.y;
    const float4* sE4f = (const float4*)sEf[w];

    float p0 = 1.f, p1 = 1.f, p2 = 1.f, p3 = 1.f;
    float r0 = 1.f, r1 = 1.f, r2 = 1.f, r3 = 1.f;
    #pragma unroll
    for (int jp = 0; jp < 16; jp += 2) {
        float4 Ev = sE4f[jp >> 1];
        float2 aA = __ldg(&t0[jp * DD + k0]);
        float2 aB = __ldg(&t0[(jp + 1) * DD + k0]);
        float2 bA = __ldg(&t1[jp * DD + k1]);
        float2 bB = __ldg(&t1[(jp + 1) * DD + k1]);
        p0 *= fmaf(Ev.x, aA.x, 1.f);
        p1 *= fmaf(Ev.y, aA.y, 1.f);
        p2 *= fmaf(Ev.z, aB.x, 1.f);
        p3 *= fmaf(Ev.w, aB.y, 1.f);
        r0 *= fmaf(Ev.x, bA.x, 1.f);
        r1 *= fmaf(Ev.y, bA.y, 1.f);
        r2 *= fmaf(Ev.z, bB.x, 1.f);
        r3 *= fmaf(Ev.w, bB.y, 1.f);
    }
    float ek0 = ebf0 * sqrtf((p0 * p1) * (p2 * p3));
    float ek1 = ebf1 * sqrtf((r0 * r1) * (r2 * r3));

    // gumbel-max in exp domain: argmax(l+g) == argmax(ek / z); keys > 0
    float z0 = -logf(u0 + 1e-9f) + 1e-9f;
    float z1 = -logf(u1 + 1e-9f) + 1e-9f;
    float key0 = ek0 / z0;
    float key1 = ek1 / z1;

    float key; int ki;
    if (key0 >= key1) { key = key0; ki = k0; } else { key = key1; ki = k1; }

    // warp sum (5 shfl) + warp argmax (redux + ballot + 1 shfl)
    float s = ek0 + ek1;
    #pragma unroll
    for (int off = 16; off; off >>= 1) s += __shfl_xor_sync(0xffffffffu, s, off);
    unsigned km   = fmono(key);
    unsigned wmax = __reduce_max_sync(0xffffffffu, km);
    unsigned ball = __ballot_sync(0xffffffffu, km == wmax);
    int      wki  = __shfl_sync(0xffffffffu, ki, __ffs(ball) - 1);
    if (lane == 0) { sredf[w] = s; sredk[w] = make_uint2(wmax, (unsigned)wki); }
    __syncthreads();                           // B2 (genuine combine)

    // ---- every thread combines 4 warp partials via broadcast LDS ----
    float Sf;
    int   kstar;
    {
        Sf = (sredf[0] + sredf[1]) + (sredf[2] + sredf[3]);
        uint2 c0 = sredk[0], c1 = sredk[1], c2 = sredk[2], c3 = sredk[3];
        uint2 mA = (c1.x > c0.x || (c1.x == c0.x && c1.y < c0.y)) ? c1 : c0;
        uint2 mB = (c3.x > c2.x || (c3.x == c2.x && c3.y < c2.y)) ? c3 : c2;
        uint2 mm = (mB.x > mA.x || (mB.x == mA.x && mB.y < mA.y)) ? mB : mA;
        kstar = (int)mm.y;
    }

    // ---- rank-1 update, per-warp redundant: E' = E * rowtable[kstar],
    //      coalesced 128B row read; R kept in a register (same in all warps) ----
    float Rt;
    {
        float xks = xs[kstar];                 // visible: written pre-B2
        const float* rowt = (xks == 0.0f) ? g_ewpR : g_ewmR;
        float mj  = __ldg(&rowt[kstar * HH + lane]);
        float E2  = E * mj;
        sE2[w][lane] = E2;
        float r = (1.f + E2) / (1.f + E);
        #pragma unroll
        for (int off = 16; off; off >>= 1) r *= __shfl_xor_sync(0xffffffffu, r, off);
        Rt = r;
        __syncwarp();
    }

    // ---- reverse pass at x_delta: tables flip only for the kstar dim ----
    const float2* t0r = (k0 == kstar) ? ((xk0 == 0.0f) ? (const float2*)g_ewm : (const float2*)g_ewp) : t0;
    const float2* t1r = (k1 == kstar) ? ((xk1 == 0.0f) ? (const float2*)g_ewm : (const float2*)g_ewp) : t1;
    const float ebr0 = (k0 == kstar) ? ((xk0 == 0.0f) ? eb0.y : eb0.x) : ebf0;
    const float ebr1 = (k1 == kstar) ? ((xk1 == 0.0f) ? eb1.y : eb1.x) : ebf1;
    const float4* sE42 = (const float4*)sE2[w];

    float q0 = 1.f, q1 = 1.f, q2 = 1.f, q3 = 1.f;
    float v0 = 1.f, v1 = 1.f, v2 = 1.f, v3 = 1.f;
    #pragma unroll
    for (int jp = 0; jp < 16; jp += 2) {
        float4 Ev = sE42[jp >> 1];
        float2 aA = __ldg(&t0r[jp * DD + k0]);
        float2 aB = __ldg(&t0r[(jp + 1) * DD + k0]);
        float2 bA = __ldg(&t1r[jp * DD + k1]);
        float2 bB = __ldg(&t1r[(jp + 1) * DD + k1]);
        q0 *= fmaf(Ev.x, aA.x, 1.f);
        q1 *= fmaf(Ev.y, aA.y, 1.f);
        q2 *= fmaf(Ev.z, aB.x, 1.f);
        q3 *= fmaf(Ev.w, aB.y, 1.f);
        v0 *= fmaf(Ev.x, bA.x, 1.f);
        v1 *= fmaf(Ev.y, bA.y, 1.f);
        v2 *= fmaf(Ev.z, bB.x, 1.f);
        v3 *= fmaf(Ev.w, bB.y, 1.f);
    }
    float er0 = ebr0 * sqrtf((q0 * q1) * (q2 * q3));
    float er1 = ebr1 * sqrtf((v0 * v1) * (v2 * v3));

    float s2 = er0 + er1;
    #pragma unroll
    for (int off = 16; off; off >>= 1) s2 += __shfl_xor_sync(0xffffffffu, s2, off);
    if (lane == 0) sredf[w] = s2;
    __syncthreads();                           // B4 (genuine combine)

    float Sr = (sredf[0] + sredf[1]) + (sredf[2] + sredf[3]);

    // ---- accept: Zf/Zr = sqrt(R) * Sf / Sr > u ----
    bool accv = sqrtf(Rt) * Sf > au * Sr;
    out[row * DD + k0] = (k0 == kstar && accv) ? (1.f - xk0) : xk0;
    out[row * DD + k1] = (k1 == kstar && accv) ? (1.f - xk1) : xk1;
}

extern "C" void kernel_launch(void* const* d_in, const int* in_sizes, int n_in,
                              void* d_out, int out_size) {
    const float* x   = (const float*)d_in[0];
    const float* W   = (const float*)d_in[1];
    const float* b   = (const float*)d_in[2];
    const float* c   = (const float*)d_in[3];
    const float* gum = (const float*)d_in[4];
    const float* acc = (const float*)d_in[5];
    float* out = (float*)d_out;

    prep_kernel<<<8 + BB / 8, 256>>>(x, W, b, c);
    gwg_kernel<<<BB, 128>>>(x, gum, acc, out);
}

// round 10
// speedup vs baseline: 1.0205x; 1.0205x over previous
#include <cuda_runtime.h>

#define BB 1024
#define DD 256
#define HH 32

// Column tables: exp(+W)/exp(-W) interleaved by j-pair, [16][DD] float2 — coalesced
// across k in the per-dim passes.  Row tables: [DD][HH] — coalesced across j for the
// rank-1 kstar-row gather.
__device__ float  g_ewp[HH * DD];
__device__ float  g_ewm[HH * DD];
__device__ float  g_ewpR[DD * HH];
__device__ float  g_ewmR[DD * HH];
__device__ float2 g_eb[DD];          // (exp(+b/2), exp(-b/2))
__device__ float  g_E[BB * HH];      // E_j(row) = exp((x@W)_j + c_j)

// Prep: blocks 0..7 build tables; blocks 8..8+BB/8-1 compute E, 8 rows per block.
__global__ __launch_bounds__(256) void prep_kernel(
    const float* __restrict__ x,
    const float* __restrict__ W,
    const float* __restrict__ b,
    const float* __restrict__ c)
{
    const int bid = blockIdx.x;
    const int tid = threadIdx.x;
    if (bid < 8) {
        for (int t = bid * 256 + tid; t < DD * HH; t += 8 * 256) {
            int d = t >> 5;
            int j = t & 31;
            float w  = W[t];
            float ep = expf(w);
            float em = expf(-w);
            int idx = (j >> 1) * (DD * 2) + d * 2 + (j & 1);
            g_ewp[idx] = ep;
            g_ewm[idx] = em;
            g_ewpR[t] = ep;          // t = d*HH + j: row-major copy
            g_ewmR[t] = em;
        }
        int t = bid * 256 + tid;
        if (t < DD) {
            float bv = b[t];
            g_eb[t] = make_float2(expf(0.5f * bv), expf(-0.5f * bv));
        }
        cudaTriggerProgrammaticLaunchCompletion();
        return;
    }

    // ---- E for 8 rows: warp w covers d in [32w,32w+32), lane = j.
    //      Each W value is loaded once and reused across 8 rows (8 masks). ----
    __shared__ float ap[8][8][32];           // [warp][row][j]
    const int row0 = (bid - 8) * 8;
    const int w    = tid >> 5;
    const int lane = tid & 31;

    unsigned m[8];
    #pragma unroll
    for (int r = 0; r < 8; ++r)
        m[r] = __ballot_sync(0xffffffffu, x[(row0 + r) * DD + w * 32 + lane] != 0.0f);

    const float* Wb = W + (w * 32) * HH + lane;
    float acc[8] = {0.f, 0.f, 0.f, 0.f, 0.f, 0.f, 0.f, 0.f};
    #pragma unroll
    for (int i = 0; i < 32; ++i) {
        float wv = Wb[i * HH];
        #pragma unroll
        for (int r = 0; r < 8; ++r)
            if (m[r] & (1u << i)) acc[r] += wv;
    }
    #pragma unroll
    for (int r = 0; r < 8; ++r) ap[w][r][lane] = acc[r];
    __syncthreads();

    // warp w finishes row (row0 + w)
    float a = c[lane];
    #pragma unroll
    for (int ww = 0; ww < 8; ++ww) a += ap[ww][w][lane];
    g_E[(row0 + w) * HH + lane] = expf(a);
    cudaTriggerProgrammaticLaunchCompletion();
}

__device__ __forceinline__ unsigned fmono(float f) {
    unsigned u = __float_as_uint(f);
    return (u & 0x80000000u) ? ~u : (u | 0x80000000u);
}

__global__ __launch_bounds__(128, 8) void gwg_kernel(
    const float* __restrict__ x,
    const float* __restrict__ gum,
    const float* __restrict__ acc,
    float* __restrict__ out)
{
    __shared__ float xs[DD];
    __shared__ __align__(16) float sEf[4][HH];   // per-warp copy of E_j
    __shared__ __align__(16) float sE2[4][HH];   // per-warp copy of E'_j
    __shared__ float sredf[4];
    __shared__ uint2 sredk[4];                   // (fmono(key), idx) per warp

    const int row  = blockIdx.x;
    const int tid  = threadIdx.x;
    const int w    = tid >> 5;
    const int lane = tid & 31;
    const int k0   = tid;          // dims tid and tid+128
    const int k1   = tid + 128;

    // prep-independent front work: harness inputs only (overlaps with prep tail)
    float  xk0 = x[row * DD + k0];
    float  xk1 = x[row * DD + k1];
    float  u0  = gum[row * DD + k0];
    float  u1  = gum[row * DD + k1];
    float  au  = acc[row];
    xs[k0] = xk0;
    xs[k1] = xk1;

    // gumbel z can be computed before prep output is needed
    float z0 = -logf(u0 + 1e-9f) + 1e-9f;
    float z1 = -logf(u1 + 1e-9f) + 1e-9f;

    // wait for prep's global writes (tables, g_eb, g_E) to be visible
    cudaGridDependencySynchronize();

    float2 eb0 = g_eb[k0];
    float2 eb1 = g_eb[k1];

    // each warp keeps its own E_lane and its own smem copy -> no cross-warp wait
    float E = g_E[row * HH + lane];
    sEf[w][lane] = E;
    __syncwarp();

    // ---- forward: p~_k = prod_j (1 + E_j e^{delta_k w_kj});  ek = eb * sqrt ----
    const float2* t0 = (const float2*)((xk0 == 0.0f) ? g_ewp : g_ewm);
    const float2* t1 = (const float2*)((xk1 == 0.0f) ? g_ewp : g_ewm);
    const float ebf0 = (xk0 == 0.0f) ? eb0.x : eb0.y;
    const float ebf1 = (xk1 == 0.0f) ? eb1.x : eb1.y;
    const float4* sE4f = (const float4*)sEf[w];

    float p0 = 1.f, p1 = 1.f, p2 = 1.f, p3 = 1.f;
    float r0 = 1.f, r1 = 1.f, r2 = 1.f, r3 = 1.f;
    #pragma unroll
    for (int jp = 0; jp < 16; jp += 2) {
        float4 Ev = sE4f[jp >> 1];
        float2 aA = __ldg(&t0[jp * DD + k0]);
        float2 aB = __ldg(&t0[(jp + 1) * DD + k0]);
        float2 bA = __ldg(&t1[jp * DD + k1]);
        float2 bB = __ldg(&t1[(jp + 1) * DD + k1]);
        p0 *= fmaf(Ev.x, aA.x, 1.f);
        p1 *= fmaf(Ev.y, aA.y, 1.f);
        p2 *= fmaf(Ev.z, aB.x, 1.f);
        p3 *= fmaf(Ev.w, aB.y, 1.f);
        r0 *= fmaf(Ev.x, bA.x, 1.f);
        r1 *= fmaf(Ev.y, bA.y, 1.f);
        r2 *= fmaf(Ev.z, bB.x, 1.f);
        r3 *= fmaf(Ev.w, bB.y, 1.f);
    }
    float ek0 = ebf0 * sqrtf((p0 * p1) * (p2 * p3));
    float ek1 = ebf1 * sqrtf((r0 * r1) * (r2 * r3));

    // gumbel-max in exp domain: argmax(l+g) == argmax(ek / z); keys > 0
    float key0 = ek0 / z0;
    float key1 = ek1 / z1;

    float key; int ki;
    if (key0 >= key1) { key = key0; ki = k0; } else { key = key1; ki = k1; }

    // warp sum (5 shfl) + warp argmax (redux + ballot + 1 shfl)
    float s = ek0 + ek1;
    #pragma unroll
    for (int off = 16; off; off >>= 1) s += __shfl_xor_sync(0xffffffffu, s, off);
    unsigned km   = fmono(key);
    unsigned wmax = __reduce_max_sync(0xffffffffu, km);
    unsigned ball = __ballot_sync(0xffffffffu, km == wmax);
    int      wki  = __shfl_sync(0xffffffffu, ki, __ffs(ball) - 1);
    if (lane == 0) { sredf[w] = s; sredk[w] = make_uint2(wmax, (unsigned)wki); }
    __syncthreads();                           // B2 (genuine combine)

    // ---- every thread combines 4 warp partials via broadcast LDS ----
    float Sf;
    int   kstar;
    {
        Sf = (sredf[0] + sredf[1]) + (sredf[2] + sredf[3]);
        uint2 c0 = sredk[0], c1 = sredk[1], c2 = sredk[2], c3 = sredk[3];
        uint2 mA = (c1.x > c0.x || (c1.x == c0.x && c1.y < c0.y)) ? c1 : c0;
        uint2 mB = (c3.x > c2.x || (c3.x == c2.x && c3.y < c2.y)) ? c3 : c2;
        uint2 mm = (mB.x > mA.x || (mB.x == mA.x && mB.y < mA.y)) ? mB : mA;
        kstar = (int)mm.y;
    }

    // ---- rank-1 update, per-warp redundant: E' = E * rowtable[kstar],
    //      coalesced 128B row read; R kept in a register (same in all warps) ----
    float Rt;
    {
        float xks = xs[kstar];                 // visible: written pre-B2
        const float* rowt = (xks == 0.0f) ? g_ewpR : g_ewmR;
        float mj  = __ldg(&rowt[kstar * HH + lane]);
        float E2  = E * mj;
        sE2[w][lane] = E2;
        float r = (1.f + E2) / (1.f + E);
        #pragma unroll
        for (int off = 16; off; off >>= 1) r *= __shfl_xor_sync(0xffffffffu, r, off);
        Rt = r;
        __syncwarp();
    }

    // ---- reverse pass at x_delta: tables flip only for the kstar dim ----
    const float2* t0r = (k0 == kstar) ? ((xk0 == 0.0f) ? (const float2*)g_ewm : (const float2*)g_ewp) : t0;
    const float2* t1r = (k1 == kstar) ? ((xk1 == 0.0f) ? (const float2*)g_ewm : (const float2*)g_ewp) : t1;
    const float ebr0 = (k0 == kstar) ? ((xk0 == 0.0f) ? eb0.y : eb0.x) : ebf0;
    const float ebr1 = (k1 == kstar) ? ((xk1 == 0.0f) ? eb1.y : eb1.x) : ebf1;
    const float4* sE42 = (const float4*)sE2[w];

    float q0 = 1.f, q1 = 1.f, q2 = 1.f, q3 = 1.f;
    float v0 = 1.f, v1 = 1.f, v2 = 1.f, v3 = 1.f;
    #pragma unroll
    for (int jp = 0; jp < 16; jp += 2) {
        float4 Ev = sE42[jp >> 1];
        float2 aA = __ldg(&t0r[jp * DD + k0]);
        float2 aB = __ldg(&t0r[(jp + 1) * DD + k0]);
        float2 bA = __ldg(&t1r[jp * DD + k1]);
        float2 bB = __ldg(&t1r[(jp + 1) * DD + k1]);
        q0 *= fmaf(Ev.x, aA.x, 1.f);
        q1 *= fmaf(Ev.y, aA.y, 1.f);
        q2 *= fmaf(Ev.z, aB.x, 1.f);
        q3 *= fmaf(Ev.w, aB.y, 1.f);
        v0 *= fmaf(Ev.x, bA.x, 1.f);
        v1 *= fmaf(Ev.y, bA.y, 1.f);
        v2 *= fmaf(Ev.z, bB.x, 1.f);
        v3 *= fmaf(Ev.w, bB.y, 1.f);
    }
    float er0 = ebr0 * sqrtf((q0 * q1) * (q2 * q3));
    float er1 = ebr1 * sqrtf((v0 * v1) * (v2 * v3));

    float s2 = er0 + er1;
    #pragma unroll
    for (int off = 16; off; off >>= 1) s2 += __shfl_xor_sync(0xffffffffu, s2, off);
    if (lane == 0) sredf[w] = s2;
    __syncthreads();                           // B4 (genuine combine)

    float Sr = (sredf[0] + sredf[1]) + (sredf[2] + sredf[3]);

    // ---- accept: Zf/Zr = sqrt(R) * Sf / Sr > u ----
    bool accv = sqrtf(Rt) * Sf > au * Sr;
    out[row * DD + k0] = (k0 == kstar && accv) ? (1.f - xk0) : xk0;
    out[row * DD + k1] = (k1 == kstar && accv) ? (1.f - xk1) : xk1;
}

extern "C" void kernel_launch(void* const* d_in, const int* in_sizes, int n_in,
                              void* d_out, int out_size) {
    const float* x   = (const float*)d_in[0];
    const float* W   = (const float*)d_in[1];
    const float* b   = (const float*)d_in[2];
    const float* c   = (const float*)d_in[3];
    const float* gum = (const float*)d_in[4];
    const float* acc = (const float*)d_in[5];
    float* out = (float*)d_out;

    prep_kernel<<<8 + BB / 8, 256>>>(x, W, b, c);

    // PDL: gwg launches as prep's blocks trigger; it does prep-independent
    // front work, then cudaGridDependencySynchronize() before reading tables.
    cudaLaunchConfig_t cfg = {};
    cfg.gridDim  = dim3(BB, 1, 1);
    cfg.blockDim = dim3(128, 1, 1);
    cfg.dynamicSmemBytes = 0;
    cfg.stream = 0;
    cudaLaunchAttribute attrs[1];
    attrs[0].id = cudaLaunchAttributeProgrammaticStreamSerialization;
    attrs[0].val.programmaticStreamSerializationAllowed = 1;
    cfg.attrs = attrs;
    cfg.numAttrs = 1;
    cudaLaunchKernelEx(&cfg, gwg_kernel, x, gum, acc, out);
}